// round 5
// baseline (speedup 1.0000x reference)
#include <cuda_runtime.h>
#include <math.h>

// Exact exchangeable-group reduction of a 132-dim Kalman filter to 4x4 blocks,
// plus bit-exact Riccati fixed-point freezing: the covariance recursion is
// data-independent and contractive; once the fp32 state reproduces itself
// bitwise, all gains are constant and the remaining steps only run the 6-dim
// mean/likelihood recursion with frozen matrices (mathematically identical).

__device__ __forceinline__ float inv4f(const float A[4][4], float R[4][4]) {
    float a00=A[0][0], a01=A[0][1], a02=A[0][2], a03=A[0][3];
    float a10=A[1][0], a11=A[1][1], a12=A[1][2], a13=A[1][3];
    float a20=A[2][0], a21=A[2][1], a22=A[2][2], a23=A[2][3];
    float a30=A[3][0], a31=A[3][1], a32=A[3][2], a33=A[3][3];
    float s0=a00*a11-a10*a01, s1=a00*a12-a10*a02, s2=a00*a13-a10*a03;
    float s3=a01*a12-a11*a02, s4=a01*a13-a11*a03, s5=a02*a13-a12*a03;
    float c5=a22*a33-a32*a23, c4=a21*a33-a31*a23, c3=a21*a32-a31*a22;
    float c2=a20*a33-a30*a23, c1=a20*a32-a30*a22, c0=a20*a31-a30*a21;
    float det = s0*c5 - s1*c4 + s2*c3 + s3*c2 - s4*c1 + s5*c0;
    float id = __fdividef(1.0f, det);
    R[0][0]=( a11*c5 - a12*c4 + a13*c3)*id;
    R[0][1]=(-a01*c5 + a02*c4 - a03*c3)*id;
    R[0][2]=( a31*s5 - a32*s4 + a33*s3)*id;
    R[0][3]=(-a21*s5 + a22*s4 - a23*s3)*id;
    R[1][0]=(-a10*c5 + a12*c2 - a13*c1)*id;
    R[1][1]=( a00*c5 - a02*c2 + a03*c1)*id;
    R[1][2]=(-a30*s5 + a32*s2 - a33*s1)*id;
    R[1][3]=( a20*s5 - a22*s2 + a23*s1)*id;
    R[2][0]=( a10*c4 - a11*c2 + a13*c0)*id;
    R[2][1]=(-a00*c4 + a01*c2 - a03*c0)*id;
    R[2][2]=( a30*s4 - a31*s2 + a33*s0)*id;
    R[2][3]=(-a20*s4 + a21*s2 - a23*s0)*id;
    R[3][0]=(-a10*c3 + a11*c1 - a12*c0)*id;
    R[3][1]=( a00*c3 - a01*c1 + a02*c0)*id;
    R[3][2]=(-a30*s3 + a31*s1 - a32*s0)*id;
    R[3][3]=( a20*s3 - a21*s1 + a22*s0)*id;
    return det;
}

__global__ void __launch_bounds__(256, 1)
hmm_kernel(const float* __restrict__ track,
           const float* __restrict__ bias_scales,
           const float* __restrict__ obs_noise_p,
           const float* __restrict__ trans_noise_p,
           float* __restrict__ out, int out_size)
{
    __shared__ float sLam4[4];
    __shared__ float sPhi[4][4];
    __shared__ float sE[4][2];
    __shared__ float sSsInv[2][2];
    __shared__ float sPu[3];
    __shared__ double sll;

    if (threadIdx.x == 0) {
        const float c0 = bias_scales[0];
        const float c1 = bias_scales[1];
        const float on = obs_noise_p[0];
        const float tn = trans_noise_p[0];
        const float sig2 = on*on;
        const float q = tn*tn;
        const float n = 32.0f;
        const float LOG2PI = 1.8378770664093454836f;

        float a[4]   = {c0, c1, c0, c1};
        float B[4][4]; float C[4][2];
#pragma unroll
        for (int g=0; g<4; ++g) { C[g][0]=0.0f; C[g][1]=0.0f;
#pragma unroll
            for (int h=0; h<4; ++h) B[g][h]=0.0f; }
        float p00=1.0f, p02=0.0f, p22=1.0f;
        float pu00=1.0f, pu01=0.0f, pu11=1.0f;
        float beta[4] = {0.0f,0.0f,0.0f,0.0f};
        float mu0=0.0f, mu2=0.0f;
        double ll = 0.0;

        // persisted across the loop: frozen gains after fixed-point detection
        float U[4][4], Vr[4][2], T4[4][4];
        float d0 = 0.0f, d1 = 0.0f, detX = 1.0f;

        int t = 0;
        for (; t < 2048; ++t) {
            // snapshot covariance state for fixed-point detection
            float pa0=a[0], pa1=a[1];
            float pB[4][4], pC[4][2];
#pragma unroll
            for (int g=0; g<4; ++g) { pC[g][0]=C[g][0]; pC[g][1]=C[g][1];
#pragma unroll
                for (int h=0; h<4; ++h) pB[g][h]=B[g][h]; }
            float pp00=p00, pp02=p02, pp22=p22;

            const float2 yv = *reinterpret_cast<const float2*>(track + 2*t);
            const float y0 = yv.x;
            const float y1 = yv.y;

            // ---- predict ----
            mu0 += mu2;
            {
                float n00 = p00 + 2.0f*p02 + p22 + q*(1.0f/3.0f);
                float n02 = p02 + p22 + 0.5f*q;
                float n22 = p22 + q;
                p00=n00; p02=n02; p22=n22;
                float m00 = pu00 + 2.0f*pu01 + pu11 + q*(1.0f/3.0f);
                float m01 = pu01 + pu11 + 0.5f*q;
                float m11 = pu11 + q;
                pu00=m00; pu01=m01; pu11=m11;
            }
#pragma unroll
            for (int g=0; g<4; ++g) C[g][0] += C[g][1];

            // ---- build U, Vr, W ----
            float P2m[2][2] = {{p00,p02},{p02,p22}};
            float W[4][4];
#pragma unroll
            for (int g=0; g<4; ++g) {
                const int rg = g>>1;
#pragma unroll
                for (int h=0; h<4; ++h) U[g][h] = B[g][h] + C[h][rg];
                Vr[g][0] = C[g][0] + P2m[rg][0];
                Vr[g][1] = C[g][1] + P2m[rg][1];
            }
#pragma unroll
            for (int g=0; g<4; ++g)
#pragma unroll
                for (int h=0; h<4; ++h) W[g][h] = U[g][h] + Vr[g][h>>1];

            d0 = a[0] + sig2; d1 = a[1] + sig2;
            float lam[4];
            lam[0] = __fdividef(1.0f, d0);
            lam[1] = __fdividef(1.0f, d1);
            lam[2]=lam[0]; lam[3]=lam[1];

            // ---- Woodbury core ----
            float X[4][4];
#pragma unroll
            for (int g=0; g<4; ++g) {
                const float nl = n*lam[g];
#pragma unroll
                for (int h=0; h<4; ++h)
                    X[g][h] = ((g==h)?1.0f:0.0f) + nl*W[g][h];
            }
            float Y[4][4];
            detX = inv4f(X, Y);

            float Gm[4][4];
#pragma unroll
            for (int g=0; g<4; ++g)
#pragma unroll
                for (int h=0; h<4; ++h) {
                    float wy = 0.0f;
#pragma unroll
                    for (int k=0; k<4; ++k) wy += W[g][k]*Y[k][h];
                    float gm = lam[g]*wy*lam[h];
                    Gm[g][h] = gm;
                    T4[g][h] = ((g==h)?lam[g]:0.0f) - n*gm;
                }

            // ---- innovation + likelihood ----
            float v4[4];
            v4[0] = y0 - beta[0] - mu0;
            v4[1] = y1 - beta[1] - mu0;
            v4[2] = y0 - beta[2] - mu2;
            v4[3] = y1 - beta[3] - mu2;
            float w4[4];
#pragma unroll
            for (int g=0; g<4; ++g) {
                float s = 0.0f;
#pragma unroll
                for (int h=0; h<4; ++h) s += T4[g][h]*v4[h];
                w4[g] = s;
            }
            float quad = n*(v4[0]*w4[0]+v4[1]*w4[1]+v4[2]*w4[2]+v4[3]*w4[3]);
            float step_ll = 128.0f*LOG2PI + 64.0f*(__logf(d0) + __logf(d1))
                          + __logf(detX) + quad;
            ll -= 0.5 * (double)step_ll;

            // ---- mean update ----
            float Utw[4], Vtw0=0.0f, Vtw1=0.0f;
#pragma unroll
            for (int h=0; h<4; ++h) {
                float s=0.0f;
#pragma unroll
                for (int g=0; g<4; ++g) s += U[g][h]*w4[g];
                Utw[h]=s;
            }
#pragma unroll
            for (int g=0; g<4; ++g) { Vtw0 += Vr[g][0]*w4[g]; Vtw1 += Vr[g][1]*w4[g]; }
#pragma unroll
            for (int g=0; g<4; ++g) beta[g] += a[g]*w4[g] + n*Utw[g];
            mu0 += n*Vtw0; mu2 += n*Vtw1;

            // ---- covariance update ----
            float Z[4][4];
#pragma unroll
            for (int g=0; g<4; ++g)
#pragma unroll
                for (int h=0; h<4; ++h) {
                    float s=0.0f;
#pragma unroll
                    for (int k=0; k<4; ++k) s += T4[g][k]*U[k][h];
                    Z[g][h] = s - Gm[g][h]*a[h];
                }
            float Bn[4][4];
#pragma unroll
            for (int g=0; g<4; ++g)
#pragma unroll
                for (int h=0; h<4; ++h) {
                    float s=0.0f;
#pragma unroll
                    for (int k=0; k<4; ++k) s += U[k][g]*Z[k][h];
                    Bn[g][h] = B[g][h] - (a[g]*Z[g][h] + U[h][g]*a[h]*lam[h] + n*s);
                }
#pragma unroll
            for (int g=0; g<4; ++g)
#pragma unroll
                for (int h=0; h<4; ++h) B[g][h] = 0.5f*(Bn[g][h]+Bn[h][g]);

            float Vt[4][2];
#pragma unroll
            for (int g=0; g<4; ++g) {
                float t0=0.0f, t1=0.0f;
#pragma unroll
                for (int k=0; k<4; ++k) { t0 += T4[g][k]*Vr[k][0]; t1 += T4[g][k]*Vr[k][1]; }
                Vt[g][0]=t0; Vt[g][1]=t1;
            }
#pragma unroll
            for (int g=0; g<4; ++g) {
                float t0=0.0f, t1=0.0f;
#pragma unroll
                for (int k=0; k<4; ++k) { t0 += U[k][g]*Vt[k][0]; t1 += U[k][g]*Vt[k][1]; }
                C[g][0] -= a[g]*Vt[g][0] + n*t0;
                C[g][1] -= a[g]*Vt[g][1] + n*t1;
            }
            float s00=0.0f, s01=0.0f, s10=0.0f, s11=0.0f;
#pragma unroll
            for (int g=0; g<4; ++g) {
                s00 += Vr[g][0]*Vt[g][0];
                s01 += Vr[g][0]*Vt[g][1];
                s10 += Vr[g][1]*Vt[g][0];
                s11 += Vr[g][1]*Vt[g][1];
            }
            p00 -= n*s00; p22 -= n*s11; p02 -= 0.5f*n*(s01+s10);

            a[0] *= sig2*lam[0]; a[1] *= sig2*lam[1]; a[2]=a[0]; a[3]=a[1];

            // ---- bitwise fixed-point detection ----
            bool same = (a[0]==pa0) & (a[1]==pa1)
                      & (p00==pp00) & (p02==pp02) & (p22==pp22);
#pragma unroll
            for (int g=0; g<4; ++g) {
                same = same & (C[g][0]==pC[g][0]) & (C[g][1]==pC[g][1]);
#pragma unroll
                for (int h=0; h<4; ++h) same = same & (B[g][h]==pB[g][h]);
            }
            if (same) { ++t; break; }
        }

        // ---- frozen tail: constant gains, 6-dim mean + quad only ----
        if (t < 2048) {
            const float step_base = 128.0f*LOG2PI + 64.0f*(__logf(d0) + __logf(d1))
                                  + __logf(detX);
            double qacc = 0.0;
            int cnt = 0;
            for (; t < 2048; ++t) {
                const float2 yv = *reinterpret_cast<const float2*>(track + 2*t);
                mu0 += mu2;
                {
                    float m00 = pu00 + 2.0f*pu01 + pu11 + q*(1.0f/3.0f);
                    float m01 = pu01 + pu11 + 0.5f*q;
                    float m11 = pu11 + q;
                    pu00=m00; pu01=m01; pu11=m11;
                }
                float v0 = yv.x - beta[0] - mu0;
                float v1 = yv.y - beta[1] - mu0;
                float v2 = yv.x - beta[2] - mu2;
                float v3 = yv.y - beta[3] - mu2;
                float w0 = T4[0][0]*v0 + T4[0][1]*v1 + T4[0][2]*v2 + T4[0][3]*v3;
                float w1 = T4[1][0]*v0 + T4[1][1]*v1 + T4[1][2]*v2 + T4[1][3]*v3;
                float w2 = T4[2][0]*v0 + T4[2][1]*v1 + T4[2][2]*v2 + T4[2][3]*v3;
                float w3 = T4[3][0]*v0 + T4[3][1]*v1 + T4[3][2]*v2 + T4[3][3]*v3;
                qacc += (double)(v0*w0 + v1*w1 + v2*w2 + v3*w3);
                float Ut0 = U[0][0]*w0 + U[1][0]*w1 + U[2][0]*w2 + U[3][0]*w3;
                float Ut1 = U[0][1]*w0 + U[1][1]*w1 + U[2][1]*w2 + U[3][1]*w3;
                float Ut2 = U[0][2]*w0 + U[1][2]*w1 + U[2][2]*w2 + U[3][2]*w3;
                float Ut3 = U[0][3]*w0 + U[1][3]*w1 + U[2][3]*w2 + U[3][3]*w3;
                beta[0] += a[0]*w0 + n*Ut0;
                beta[1] += a[1]*w1 + n*Ut1;
                beta[2] += a[2]*w2 + n*Ut2;
                beta[3] += a[3]*w3 + n*Ut3;
                mu0 += n*(Vr[0][0]*w0 + Vr[1][0]*w1 + Vr[2][0]*w2 + Vr[3][0]*w3);
                mu2 += n*(Vr[0][1]*w0 + Vr[1][1]*w1 + Vr[2][1]*w2 + Vr[3][1]*w3);
                ++cnt;
            }
            ll -= 0.5 * ((double)cnt * (double)step_base + (double)n * qacc);
        }

        // ---- final structured inverse of the 132x132 filtered covariance ----
        float La[4] = {__fdividef(1.0f,a[0]), __fdividef(1.0f,a[1]),
                       __fdividef(1.0f,a[2]), __fdividef(1.0f,a[3])};
        float Xb[4][4];
#pragma unroll
        for (int g=0; g<4; ++g)
#pragma unroll
            for (int h=0; h<4; ++h)
                Xb[g][h] = ((g==h)?1.0f:0.0f) + 32.0f*La[g]*B[g][h];
        float Yb[4][4]; inv4f(Xb, Yb);
        float G[4][4];
#pragma unroll
        for (int g=0; g<4; ++g)
#pragma unroll
            for (int h=0; h<4; ++h) {
                float s=0.0f;
#pragma unroll
                for (int k=0; k<4; ++k) s += B[g][k]*Yb[k][h];
                G[g][h] = La[g]*s*La[h];
            }
        float M4[4][4];
#pragma unroll
        for (int g=0; g<4; ++g)
#pragma unroll
            for (int h=0; h<4; ++h)
                M4[g][h] = ((g==h)?La[g]:0.0f) - 32.0f*G[g][h];
        float MC[4][2];
#pragma unroll
        for (int g=0; g<4; ++g) {
            float t0=0.0f, t1=0.0f;
#pragma unroll
            for (int k=0; k<4; ++k) { t0 += M4[g][k]*C[k][0]; t1 += M4[g][k]*C[k][1]; }
            MC[g][0]=t0; MC[g][1]=t1;
        }
        float ss00=p00, ss01=p02, ss11=p22;
#pragma unroll
        for (int g=0; g<4; ++g) {
            ss00 -= 32.0f*C[g][0]*MC[g][0];
            ss01 -= 32.0f*C[g][0]*MC[g][1];
            ss11 -= 32.0f*C[g][1]*MC[g][1];
        }
        {
            float det = ss00*ss11 - ss01*ss01;
            float id = __fdividef(1.0f, det);
            sSsInv[0][0] =  ss11*id;
            sSsInv[0][1] = -ss01*id;
            sSsInv[1][0] = -ss01*id;
            sSsInv[1][1] =  ss00*id;
        }
#pragma unroll
        for (int g=0; g<4; ++g) {
            float e0 = -(MC[g][0]*sSsInv[0][0] + MC[g][1]*sSsInv[1][0]);
            float e1 = -(MC[g][0]*sSsInv[0][1] + MC[g][1]*sSsInv[1][1]);
            sE[g][0]=e0; sE[g][1]=e1;
        }
#pragma unroll
        for (int g=0; g<4; ++g)
#pragma unroll
            for (int h=0; h<4; ++h)
                sPhi[g][h] = -G[g][h] - (sE[g][0]*MC[h][0] + sE[g][1]*MC[h][1]);
#pragma unroll
        for (int g=0; g<4; ++g) sLam4[g] = La[g];
        {
            float det = pu00*pu11 - pu01*pu01;
            float id = __fdividef(1.0f, det);
            sPu[0] =  pu11*id;
            sPu[1] = -pu01*id;
            sPu[2] =  pu00*id;
        }
        sll = ll;
    }

    __syncthreads();

    // ---- expand to the 132x132 precision matrix (+ ll at out[0]) ----
    const int off = (out_size >= 17425) ? 1 : 0;
    if (threadIdx.x == 0 && off) out[0] = (float)sll;

    for (int e = threadIdx.x; e < 17424; e += blockDim.x) {
        int r = e / 132, c = e % 132;
        float val = 0.0f;
        if (r < 128 && c < 128) {
            int g = (r & 1) + ((r >= 64) ? 2 : 0);
            int h = (c & 1) + ((c >= 64) ? 2 : 0);
            val = sPhi[g][h];
            if (r == c) val += sLam4[g];
        } else if (r < 128) {
            int g = (r & 1) + ((r >= 64) ? 2 : 0);
            int j = c - 128;
            if (j == 0) val = sE[g][0];
            else if (j == 2) val = sE[g][1];
        } else if (c < 128) {
            int h = (c & 1) + ((c >= 64) ? 2 : 0);
            int i = r - 128;
            if (i == 0) val = sE[h][0];
            else if (i == 2) val = sE[h][1];
        } else {
            int i = r - 128, j = c - 128;
            if ((i == 0 || i == 2) && (j == 0 || j == 2))
                val = sSsInv[i >> 1][j >> 1];
            else if (i == 1 && j == 1) val = sPu[0];
            else if ((i == 1 && j == 3) || (i == 3 && j == 1)) val = sPu[1];
            else if (i == 3 && j == 3) val = sPu[2];
        }
        out[off + e] = (float)val;
    }
}

extern "C" void kernel_launch(void* const* d_in, const int* in_sizes, int n_in,
                              void* d_out, int out_size) {
    const float* track       = (const float*)d_in[0];
    const float* bias_scales = (const float*)d_in[1];
    const float* obs_noise   = (const float*)d_in[2];
    const float* trans_noise = (const float*)d_in[3];
    float* out = (float*)d_out;
    hmm_kernel<<<1, 256>>>(track, bias_scales, obs_noise, trans_noise, out, out_size);
}

// round 6
// speedup vs baseline: 1.4570x; 1.4570x over previous
#include <cuda_runtime.h>
#include <math.h>

// Exact exchangeable-group reduction of a 132-dim Kalman filter (64 sensors x
// 2D obs + 4 NCV states) to 4x4/4x2/2x2 block recursion. This round:
//  - T4 = (D + nW)^{-1} computed by direct symmetric 4x4 inverse
//    (replaces Woodbury X/Y/Gm chain); logdet folded accordingly.
//  - Bn symmetric: 10 entries computed, mirrored.
//  - (s1,s3) covariance closed-form (polynomial in t), out of the loop.

__global__ void __launch_bounds__(256, 1)
hmm_kernel(const float* __restrict__ track,
           const float* __restrict__ bias_scales,
           const float* __restrict__ obs_noise_p,
           const float* __restrict__ trans_noise_p,
           float* __restrict__ out, int out_size)
{
    __shared__ float sLam4[4];
    __shared__ float sPhi[4][4];
    __shared__ float sE[4][2];
    __shared__ float sSsInv[2][2];
    __shared__ float sPu[3];
    __shared__ double sll;

    if (threadIdx.x == 0) {
        const float c0 = bias_scales[0];
        const float c1 = bias_scales[1];
        const float on = obs_noise_p[0];
        const float tn = trans_noise_p[0];
        const float sig2 = on*on;
        const float q = tn*tn;
        const float n = 32.0f;
        const float inv_n = 0.03125f;
        const float LOG2PI = 1.8378770664093454836f;

        float a[4]   = {c0, c1, c0, c1};
        float B[4][4]; float C[4][2];
#pragma unroll
        for (int g=0; g<4; ++g) { C[g][0]=0.0f; C[g][1]=0.0f;
#pragma unroll
            for (int h=0; h<4; ++h) B[g][h]=0.0f; }
        float p00=1.0f, p02=0.0f, p22=1.0f;
        float beta[4] = {0.0f,0.0f,0.0f,0.0f};
        float mu0=0.0f, mu2=0.0f;
        double ll = 0.0;

        for (int t = 0; t < 2048; ++t) {
            const float2 yv = *reinterpret_cast<const float2*>(track + 2*t);
            const float y0 = yv.x;
            const float y1 = yv.y;

            // ---- predict ----
            mu0 += mu2;
            {
                float n00 = p00 + 2.0f*p02 + p22 + q*(1.0f/3.0f);
                float n02 = p02 + p22 + 0.5f*q;
                float n22 = p22 + q;
                p00=n00; p02=n02; p22=n22;
            }
#pragma unroll
            for (int g=0; g<4; ++g) C[g][0] += C[g][1];

            // ---- build U, Vr ----
            float P2m[2][2] = {{p00,p02},{p02,p22}};
            float U[4][4], Vr[4][2];
#pragma unroll
            for (int g=0; g<4; ++g) {
                const int rg = g>>1;
#pragma unroll
                for (int h=0; h<4; ++h) U[g][h] = B[g][h] + C[h][rg];
                Vr[g][0] = C[g][0] + P2m[rg][0];
                Vr[g][1] = C[g][1] + P2m[rg][1];
            }

            const float d0 = a[0] + sig2, d1 = a[1] + sig2;
            float lam0 = __fdividef(1.0f, d0);
            float lam1 = __fdividef(1.0f, d1);
            float lam[4] = {lam0, lam1, lam0, lam1};

            // ---- M = D + n W (symmetric, upper triangle) ----
            // W[g][h] = U[g][h] + Vr[g][h>>1]  (symmetric)
            float m00 = d0 + n*(U[0][0] + Vr[0][0]);
            float m01 =      n*(U[0][1] + Vr[0][0]);
            float m02 =      n*(U[0][2] + Vr[0][1]);
            float m03 =      n*(U[0][3] + Vr[0][1]);
            float m11 = d1 + n*(U[1][1] + Vr[1][0]);
            float m12 =      n*(U[1][2] + Vr[1][1]);
            float m13 =      n*(U[1][3] + Vr[1][1]);
            float m22 = d0 + n*(U[2][2] + Vr[2][1]);
            float m23 =      n*(U[2][3] + Vr[2][1]);
            float m33 = d1 + n*(U[3][3] + Vr[3][1]);

            // ---- symmetric 4x4 inverse: T4 = M^{-1}, detM ----
            float s0 = m00*m11 - m01*m01;
            float s1 = m00*m12 - m01*m02;
            float s2 = m00*m13 - m01*m03;
            float s3 = m01*m12 - m11*m02;
            float s4 = m01*m13 - m11*m03;
            float s5 = m02*m13 - m12*m03;
            float c5 = m22*m33 - m23*m23;
            float c4 = m12*m33 - m13*m23;
            float c3 = m12*m23 - m13*m22;
            float c2 = m02*m33 - m03*m23;
            float c1 = m02*m23 - m03*m22;
            float c0v= m02*m13 - m03*m12;
            float detM = s0*c5 - s1*c4 + s2*c3 + s3*c2 - s4*c1 + s5*c0v;
            float id = __fdividef(1.0f, detM);
            float T4[4][4];
            T4[0][0] = ( m11*c5 - m12*c4 + m13*c3)*id;
            T4[0][1] = (-m01*c5 + m02*c4 - m03*c3)*id;
            T4[0][2] = ( m13*s5 - m23*s4 + m33*s3)*id;
            T4[0][3] = (-m12*s5 + m22*s4 - m23*s3)*id;
            T4[1][1] = ( m00*c5 - m02*c2 + m03*c1)*id;
            T4[1][2] = (-m03*s5 + m23*s2 - m33*s1)*id;
            T4[1][3] = ( m02*s5 - m22*s2 + m23*s1)*id;
            T4[2][2] = ( m03*s4 - m13*s2 + m33*s0)*id;
            T4[2][3] = (-m02*s4 + m12*s2 - m23*s0)*id;
            T4[3][3] = ( m02*s3 - m12*s1 + m22*s0)*id;
            T4[1][0]=T4[0][1]; T4[2][0]=T4[0][2]; T4[3][0]=T4[0][3];
            T4[2][1]=T4[1][2]; T4[3][1]=T4[1][3]; T4[3][2]=T4[2][3];

            // ---- innovation + likelihood ----
            float v4[4];
            v4[0] = y0 - beta[0] - mu0;
            v4[1] = y1 - beta[1] - mu0;
            v4[2] = y0 - beta[2] - mu2;
            v4[3] = y1 - beta[3] - mu2;
            float w4[4];
#pragma unroll
            for (int g=0; g<4; ++g) {
                float s = 0.0f;
#pragma unroll
                for (int h=0; h<4; ++h) s += T4[g][h]*v4[h];
                w4[g] = s;
            }
            float quad = n*(v4[0]*w4[0]+v4[1]*w4[1]+v4[2]*w4[2]+v4[3]*w4[3]);
            // 64*(ld0+ld1) + log det(I+nLamW) = 62*(ld0+ld1) + log detM
            float step_ll = 128.0f*LOG2PI + 62.0f*(__logf(d0) + __logf(d1))
                          + __logf(detM) + quad;
            ll -= 0.5 * (double)step_ll;

            // ---- mean update ----
            float Utw[4], Vtw0=0.0f, Vtw1=0.0f;
#pragma unroll
            for (int h=0; h<4; ++h) {
                float s=0.0f;
#pragma unroll
                for (int g=0; g<4; ++g) s += U[g][h]*w4[g];
                Utw[h]=s;
            }
#pragma unroll
            for (int g=0; g<4; ++g) { Vtw0 += Vr[g][0]*w4[g]; Vtw1 += Vr[g][1]*w4[g]; }
#pragma unroll
            for (int g=0; g<4; ++g) beta[g] += a[g]*w4[g] + n*Utw[g];
            mu0 += n*Vtw0; mu2 += n*Vtw1;

            // ---- covariance update ----
            // Gm = (lam*delta - T4)/n folded: Z = T4*U + (a_h/n)*T4 - delta*(a lam /n)
            float alam[4]  = {a[0]*lam[0], a[1]*lam[1], a[2]*lam[2], a[3]*lam[3]};
            float ainvn[4] = {a[0]*inv_n, a[1]*inv_n, a[2]*inv_n, a[3]*inv_n};
            float Z[4][4];
#pragma unroll
            for (int g=0; g<4; ++g)
#pragma unroll
                for (int h=0; h<4; ++h) {
                    float s = ainvn[h]*T4[g][h];
#pragma unroll
                    for (int k=0; k<4; ++k) s += T4[g][k]*U[k][h];
                    if (g==h) s -= alam[g]*inv_n;
                    Z[g][h] = s;
                }
            // Bn symmetric: upper triangle only, mirror.
            float Bn[4][4];
#pragma unroll
            for (int g=0; g<4; ++g)
#pragma unroll
                for (int h=g; h<4; ++h) {
                    float s=0.0f;
#pragma unroll
                    for (int k=0; k<4; ++k) s += U[k][g]*Z[k][h];
                    float v = B[g][h] - (a[g]*Z[g][h] + U[h][g]*alam[h] + n*s);
                    Bn[g][h] = v; Bn[h][g] = v;
                }
#pragma unroll
            for (int g=0; g<4; ++g)
#pragma unroll
                for (int h=0; h<4; ++h) B[g][h] = Bn[g][h];

            float Vt[4][2];
#pragma unroll
            for (int g=0; g<4; ++g) {
                float t0=0.0f, t1=0.0f;
#pragma unroll
                for (int k=0; k<4; ++k) { t0 += T4[g][k]*Vr[k][0]; t1 += T4[g][k]*Vr[k][1]; }
                Vt[g][0]=t0; Vt[g][1]=t1;
            }
#pragma unroll
            for (int g=0; g<4; ++g) {
                float t0=0.0f, t1=0.0f;
#pragma unroll
                for (int k=0; k<4; ++k) { t0 += U[k][g]*Vt[k][0]; t1 += U[k][g]*Vt[k][1]; }
                C[g][0] -= a[g]*Vt[g][0] + n*t0;
                C[g][1] -= a[g]*Vt[g][1] + n*t1;
            }
            float s00=0.0f, s01=0.0f, s10=0.0f, s11=0.0f;
#pragma unroll
            for (int g=0; g<4; ++g) {
                s00 += Vr[g][0]*Vt[g][0];
                s01 += Vr[g][0]*Vt[g][1];
                s10 += Vr[g][1]*Vt[g][0];
                s11 += Vr[g][1]*Vt[g][1];
            }
            p00 -= n*s00; p22 -= n*s11; p02 -= 0.5f*n*(s01+s10);

            a[0] *= sig2*lam[0]; a[1] *= sig2*lam[1]; a[2]=a[0]; a[3]=a[1];
        }

        // ---- (s1,s3) covariance closed form after 2048 steps ----
        // P_t = F^t P0 F^t^T + q * sum_{i=0}^{t-1} F^i Q2 F^i^T, F=[[1,1],[0,1]]
        double pu00, pu01, pu11;
        {
            const double td = 2048.0;
            const double qd = (double)q;
            double sum00 = td/3.0 + td*(td-1.0)/2.0 + (td-1.0)*td*(2.0*td-1.0)/6.0;
            double sum01 = td/2.0 + td*(td-1.0)/2.0;
            pu00 = 1.0 + td*td + qd*sum00;
            pu01 = td + qd*sum01;
            pu11 = 1.0 + qd*td;
        }

        // ---- final structured inverse of the 132x132 filtered covariance ----
        float La[4] = {__fdividef(1.0f,a[0]), __fdividef(1.0f,a[1]),
                       __fdividef(1.0f,a[2]), __fdividef(1.0f,a[3])};
        float Xb[4][4];
#pragma unroll
        for (int g=0; g<4; ++g)
#pragma unroll
            for (int h=0; h<4; ++h)
                Xb[g][h] = ((g==h)?1.0f:0.0f) + 32.0f*La[g]*B[g][h];
        // general 4x4 inverse of Xb (not symmetric)
        float Yb[4][4];
        {
            float a00=Xb[0][0], a01=Xb[0][1], a02=Xb[0][2], a03=Xb[0][3];
            float a10=Xb[1][0], a11=Xb[1][1], a12=Xb[1][2], a13=Xb[1][3];
            float a20=Xb[2][0], a21=Xb[2][1], a22=Xb[2][2], a23=Xb[2][3];
            float a30=Xb[3][0], a31=Xb[3][1], a32=Xb[3][2], a33=Xb[3][3];
            float s0=a00*a11-a10*a01, s1=a00*a12-a10*a02, s2=a00*a13-a10*a03;
            float s3=a01*a12-a11*a02, s4=a01*a13-a11*a03, s5=a02*a13-a12*a03;
            float c5=a22*a33-a32*a23, c4=a21*a33-a31*a23, c3=a21*a32-a31*a22;
            float c2=a20*a33-a30*a23, c1=a20*a32-a30*a22, c0=a20*a31-a30*a21;
            float det = s0*c5 - s1*c4 + s2*c3 + s3*c2 - s4*c1 + s5*c0;
            float id = __fdividef(1.0f, det);
            Yb[0][0]=( a11*c5 - a12*c4 + a13*c3)*id;
            Yb[0][1]=(-a01*c5 + a02*c4 - a03*c3)*id;
            Yb[0][2]=( a31*s5 - a32*s4 + a33*s3)*id;
            Yb[0][3]=(-a21*s5 + a22*s4 - a23*s3)*id;
            Yb[1][0]=(-a10*c5 + a12*c2 - a13*c1)*id;
            Yb[1][1]=( a00*c5 - a02*c2 + a03*c1)*id;
            Yb[1][2]=(-a30*s5 + a32*s2 - a33*s1)*id;
            Yb[1][3]=( a20*s5 - a22*s2 + a23*s1)*id;
            Yb[2][0]=( a10*c4 - a11*c2 + a13*c0)*id;
            Yb[2][1]=(-a00*c4 + a01*c2 - a03*c0)*id;
            Yb[2][2]=( a30*s4 - a31*s2 + a33*s0)*id;
            Yb[2][3]=(-a20*s4 + a21*s2 - a23*s0)*id;
            Yb[3][0]=(-a10*c3 + a11*c1 - a12*c0)*id;
            Yb[3][1]=( a00*c3 - a01*c1 + a02*c0)*id;
            Yb[3][2]=(-a30*s3 + a31*s1 - a32*s0)*id;
            Yb[3][3]=( a20*s3 - a21*s1 + a22*s0)*id;
        }
        float G[4][4];
#pragma unroll
        for (int g=0; g<4; ++g)
#pragma unroll
            for (int h=0; h<4; ++h) {
                float s=0.0f;
#pragma unroll
                for (int k=0; k<4; ++k) s += B[g][k]*Yb[k][h];
                G[g][h] = La[g]*s*La[h];
            }
        float M4[4][4];
#pragma unroll
        for (int g=0; g<4; ++g)
#pragma unroll
            for (int h=0; h<4; ++h)
                M4[g][h] = ((g==h)?La[g]:0.0f) - 32.0f*G[g][h];
        float MC[4][2];
#pragma unroll
        for (int g=0; g<4; ++g) {
            float t0=0.0f, t1=0.0f;
#pragma unroll
            for (int k=0; k<4; ++k) { t0 += M4[g][k]*C[k][0]; t1 += M4[g][k]*C[k][1]; }
            MC[g][0]=t0; MC[g][1]=t1;
        }
        float ss00=p00, ss01=p02, ss11=p22;
#pragma unroll
        for (int g=0; g<4; ++g) {
            ss00 -= 32.0f*C[g][0]*MC[g][0];
            ss01 -= 32.0f*C[g][0]*MC[g][1];
            ss11 -= 32.0f*C[g][1]*MC[g][1];
        }
        {
            float det = ss00*ss11 - ss01*ss01;
            float id = __fdividef(1.0f, det);
            sSsInv[0][0] =  ss11*id;
            sSsInv[0][1] = -ss01*id;
            sSsInv[1][0] = -ss01*id;
            sSsInv[1][1] =  ss00*id;
        }
#pragma unroll
        for (int g=0; g<4; ++g) {
            float e0 = -(MC[g][0]*sSsInv[0][0] + MC[g][1]*sSsInv[1][0]);
            float e1 = -(MC[g][0]*sSsInv[0][1] + MC[g][1]*sSsInv[1][1]);
            sE[g][0]=e0; sE[g][1]=e1;
        }
#pragma unroll
        for (int g=0; g<4; ++g)
#pragma unroll
            for (int h=0; h<4; ++h)
                sPhi[g][h] = -G[g][h] - (sE[g][0]*MC[h][0] + sE[g][1]*MC[h][1]);
#pragma unroll
        for (int g=0; g<4; ++g) sLam4[g] = La[g];
        {
            double det = pu00*pu11 - pu01*pu01;
            double idd = 1.0/det;
            sPu[0] = (float)( pu11*idd);
            sPu[1] = (float)(-pu01*idd);
            sPu[2] = (float)( pu00*idd);
        }
        sll = ll;
    }

    __syncthreads();

    // ---- expand to the 132x132 precision matrix (+ ll at out[0]) ----
    const int off = (out_size >= 17425) ? 1 : 0;
    if (threadIdx.x == 0 && off) out[0] = (float)sll;

    for (int e = threadIdx.x; e < 17424; e += blockDim.x) {
        int r = e / 132, c = e % 132;
        float val = 0.0f;
        if (r < 128 && c < 128) {
            int g = (r & 1) + ((r >= 64) ? 2 : 0);
            int h = (c & 1) + ((c >= 64) ? 2 : 0);
            val = sPhi[g][h];
            if (r == c) val += sLam4[g];
        } else if (r < 128) {
            int g = (r & 1) + ((r >= 64) ? 2 : 0);
            int j = c - 128;
            if (j == 0) val = sE[g][0];
            else if (j == 2) val = sE[g][1];
        } else if (c < 128) {
            int h = (c & 1) + ((c >= 64) ? 2 : 0);
            int i = r - 128;
            if (i == 0) val = sE[h][0];
            else if (i == 2) val = sE[h][1];
        } else {
            int i = r - 128, j = c - 128;
            if ((i == 0 || i == 2) && (j == 0 || j == 2))
                val = sSsInv[i >> 1][j >> 1];
            else if (i == 1 && j == 1) val = sPu[0];
            else if ((i == 1 && j == 3) || (i == 3 && j == 1)) val = sPu[1];
            else if (i == 3 && j == 3) val = sPu[2];
        }
        out[off + e] = (float)val;
    }
}

extern "C" void kernel_launch(void* const* d_in, const int* in_sizes, int n_in,
                              void* d_out, int out_size) {
    const float* track       = (const float*)d_in[0];
    const float* bias_scales = (const float*)d_in[1];
    const float* obs_noise   = (const float*)d_in[2];
    const float* trans_noise = (const float*)d_in[3];
    float* out = (float*)d_out;
    hmm_kernel<<<1, 256>>>(track, bias_scales, obs_noise, trans_noise, out, out_size);
}

// round 7
// speedup vs baseline: 1.4590x; 1.0014x over previous
#include <cuda_runtime.h>
#include <math.h>

// Exact exchangeable-group reduction of a 132-dim Kalman filter (64 sensors x
// 2D obs + 4 NCV states) to 4x4/4x2/2x2 block recursion. This round:
//  - T4 = (D + nW)^{-1} computed by direct symmetric 4x4 inverse
//    (replaces Woodbury X/Y/Gm chain); logdet folded accordingly.
//  - Bn symmetric: 10 entries computed, mirrored.
//  - (s1,s3) covariance closed-form (polynomial in t), out of the loop.

__global__ void __launch_bounds__(256, 1)
hmm_kernel(const float* __restrict__ track,
           const float* __restrict__ bias_scales,
           const float* __restrict__ obs_noise_p,
           const float* __restrict__ trans_noise_p,
           float* __restrict__ out, int out_size)
{
    __shared__ float sLam4[4];
    __shared__ float sPhi[4][4];
    __shared__ float sE[4][2];
    __shared__ float sSsInv[2][2];
    __shared__ float sPu[3];
    __shared__ double sll;

    if (threadIdx.x == 0) {
        const float c0 = bias_scales[0];
        const float c1 = bias_scales[1];
        const float on = obs_noise_p[0];
        const float tn = trans_noise_p[0];
        const float sig2 = on*on;
        const float q = tn*tn;
        const float n = 32.0f;
        const float inv_n = 0.03125f;
        const float LOG2PI = 1.8378770664093454836f;

        float a[4]   = {c0, c1, c0, c1};
        float B[4][4]; float C[4][2];
#pragma unroll
        for (int g=0; g<4; ++g) { C[g][0]=0.0f; C[g][1]=0.0f;
#pragma unroll
            for (int h=0; h<4; ++h) B[g][h]=0.0f; }
        float p00=1.0f, p02=0.0f, p22=1.0f;
        float beta[4] = {0.0f,0.0f,0.0f,0.0f};
        float mu0=0.0f, mu2=0.0f;
        double ll = 0.0;

        for (int t = 0; t < 2048; ++t) {
            const float2 yv = *reinterpret_cast<const float2*>(track + 2*t);
            const float y0 = yv.x;
            const float y1 = yv.y;

            // ---- predict ----
            mu0 += mu2;
            {
                float n00 = p00 + 2.0f*p02 + p22 + q*(1.0f/3.0f);
                float n02 = p02 + p22 + 0.5f*q;
                float n22 = p22 + q;
                p00=n00; p02=n02; p22=n22;
            }
#pragma unroll
            for (int g=0; g<4; ++g) C[g][0] += C[g][1];

            // ---- build U, Vr ----
            float P2m[2][2] = {{p00,p02},{p02,p22}};
            float U[4][4], Vr[4][2];
#pragma unroll
            for (int g=0; g<4; ++g) {
                const int rg = g>>1;
#pragma unroll
                for (int h=0; h<4; ++h) U[g][h] = B[g][h] + C[h][rg];
                Vr[g][0] = C[g][0] + P2m[rg][0];
                Vr[g][1] = C[g][1] + P2m[rg][1];
            }

            const float d0 = a[0] + sig2, d1 = a[1] + sig2;
            float lam0 = __fdividef(1.0f, d0);
            float lam1 = __fdividef(1.0f, d1);
            float lam[4] = {lam0, lam1, lam0, lam1};

            // ---- M = D + n W (symmetric, upper triangle) ----
            // W[g][h] = U[g][h] + Vr[g][h>>1]  (symmetric)
            float m00 = d0 + n*(U[0][0] + Vr[0][0]);
            float m01 =      n*(U[0][1] + Vr[0][0]);
            float m02 =      n*(U[0][2] + Vr[0][1]);
            float m03 =      n*(U[0][3] + Vr[0][1]);
            float m11 = d1 + n*(U[1][1] + Vr[1][0]);
            float m12 =      n*(U[1][2] + Vr[1][1]);
            float m13 =      n*(U[1][3] + Vr[1][1]);
            float m22 = d0 + n*(U[2][2] + Vr[2][1]);
            float m23 =      n*(U[2][3] + Vr[2][1]);
            float m33 = d1 + n*(U[3][3] + Vr[3][1]);

            // ---- symmetric 4x4 inverse: T4 = M^{-1}, detM ----
            float s0 = m00*m11 - m01*m01;
            float s1 = m00*m12 - m01*m02;
            float s2 = m00*m13 - m01*m03;
            float s3 = m01*m12 - m11*m02;
            float s4 = m01*m13 - m11*m03;
            float s5 = m02*m13 - m12*m03;
            float c5 = m22*m33 - m23*m23;
            float c4 = m12*m33 - m13*m23;
            float c3 = m12*m23 - m13*m22;
            float c2 = m02*m33 - m03*m23;
            float c1 = m02*m23 - m03*m22;
            float c0v= m02*m13 - m03*m12;
            float detM = s0*c5 - s1*c4 + s2*c3 + s3*c2 - s4*c1 + s5*c0v;
            float id = __fdividef(1.0f, detM);
            float T4[4][4];
            T4[0][0] = ( m11*c5 - m12*c4 + m13*c3)*id;
            T4[0][1] = (-m01*c5 + m02*c4 - m03*c3)*id;
            T4[0][2] = ( m13*s5 - m23*s4 + m33*s3)*id;
            T4[0][3] = (-m12*s5 + m22*s4 - m23*s3)*id;
            T4[1][1] = ( m00*c5 - m02*c2 + m03*c1)*id;
            T4[1][2] = (-m03*s5 + m23*s2 - m33*s1)*id;
            T4[1][3] = ( m02*s5 - m22*s2 + m23*s1)*id;
            T4[2][2] = ( m03*s4 - m13*s2 + m33*s0)*id;
            T4[2][3] = (-m02*s4 + m12*s2 - m23*s0)*id;
            T4[3][3] = ( m02*s3 - m12*s1 + m22*s0)*id;
            T4[1][0]=T4[0][1]; T4[2][0]=T4[0][2]; T4[3][0]=T4[0][3];
            T4[2][1]=T4[1][2]; T4[3][1]=T4[1][3]; T4[3][2]=T4[2][3];

            // ---- innovation + likelihood ----
            float v4[4];
            v4[0] = y0 - beta[0] - mu0;
            v4[1] = y1 - beta[1] - mu0;
            v4[2] = y0 - beta[2] - mu2;
            v4[3] = y1 - beta[3] - mu2;
            float w4[4];
#pragma unroll
            for (int g=0; g<4; ++g) {
                float s = 0.0f;
#pragma unroll
                for (int h=0; h<4; ++h) s += T4[g][h]*v4[h];
                w4[g] = s;
            }
            float quad = n*(v4[0]*w4[0]+v4[1]*w4[1]+v4[2]*w4[2]+v4[3]*w4[3]);
            // 64*(ld0+ld1) + log det(I+nLamW) = 62*(ld0+ld1) + log detM
            float step_ll = 128.0f*LOG2PI + 62.0f*(__logf(d0) + __logf(d1))
                          + __logf(detM) + quad;
            ll -= 0.5 * (double)step_ll;

            // ---- mean update ----
            float Utw[4], Vtw0=0.0f, Vtw1=0.0f;
#pragma unroll
            for (int h=0; h<4; ++h) {
                float s=0.0f;
#pragma unroll
                for (int g=0; g<4; ++g) s += U[g][h]*w4[g];
                Utw[h]=s;
            }
#pragma unroll
            for (int g=0; g<4; ++g) { Vtw0 += Vr[g][0]*w4[g]; Vtw1 += Vr[g][1]*w4[g]; }
#pragma unroll
            for (int g=0; g<4; ++g) beta[g] += a[g]*w4[g] + n*Utw[g];
            mu0 += n*Vtw0; mu2 += n*Vtw1;

            // ---- covariance update ----
            // Gm = (lam*delta - T4)/n folded: Z = T4*U + (a_h/n)*T4 - delta*(a lam /n)
            float alam[4]  = {a[0]*lam[0], a[1]*lam[1], a[2]*lam[2], a[3]*lam[3]};
            float ainvn[4] = {a[0]*inv_n, a[1]*inv_n, a[2]*inv_n, a[3]*inv_n};
            float Z[4][4];
#pragma unroll
            for (int g=0; g<4; ++g)
#pragma unroll
                for (int h=0; h<4; ++h) {
                    float s = ainvn[h]*T4[g][h];
#pragma unroll
                    for (int k=0; k<4; ++k) s += T4[g][k]*U[k][h];
                    if (g==h) s -= alam[g]*inv_n;
                    Z[g][h] = s;
                }
            // Bn symmetric: upper triangle only, mirror.
            float Bn[4][4];
#pragma unroll
            for (int g=0; g<4; ++g)
#pragma unroll
                for (int h=g; h<4; ++h) {
                    float s=0.0f;
#pragma unroll
                    for (int k=0; k<4; ++k) s += U[k][g]*Z[k][h];
                    float v = B[g][h] - (a[g]*Z[g][h] + U[h][g]*alam[h] + n*s);
                    Bn[g][h] = v; Bn[h][g] = v;
                }
#pragma unroll
            for (int g=0; g<4; ++g)
#pragma unroll
                for (int h=0; h<4; ++h) B[g][h] = Bn[g][h];

            float Vt[4][2];
#pragma unroll
            for (int g=0; g<4; ++g) {
                float t0=0.0f, t1=0.0f;
#pragma unroll
                for (int k=0; k<4; ++k) { t0 += T4[g][k]*Vr[k][0]; t1 += T4[g][k]*Vr[k][1]; }
                Vt[g][0]=t0; Vt[g][1]=t1;
            }
#pragma unroll
            for (int g=0; g<4; ++g) {
                float t0=0.0f, t1=0.0f;
#pragma unroll
                for (int k=0; k<4; ++k) { t0 += U[k][g]*Vt[k][0]; t1 += U[k][g]*Vt[k][1]; }
                C[g][0] -= a[g]*Vt[g][0] + n*t0;
                C[g][1] -= a[g]*Vt[g][1] + n*t1;
            }
            float s00=0.0f, s01=0.0f, s10=0.0f, s11=0.0f;
#pragma unroll
            for (int g=0; g<4; ++g) {
                s00 += Vr[g][0]*Vt[g][0];
                s01 += Vr[g][0]*Vt[g][1];
                s10 += Vr[g][1]*Vt[g][0];
                s11 += Vr[g][1]*Vt[g][1];
            }
            p00 -= n*s00; p22 -= n*s11; p02 -= 0.5f*n*(s01+s10);

            a[0] *= sig2*lam[0]; a[1] *= sig2*lam[1]; a[2]=a[0]; a[3]=a[1];
        }

        // ---- (s1,s3) covariance closed form after 2048 steps ----
        // P_t = F^t P0 F^t^T + q * sum_{i=0}^{t-1} F^i Q2 F^i^T, F=[[1,1],[0,1]]
        double pu00, pu01, pu11;
        {
            const double td = 2048.0;
            const double qd = (double)q;
            double sum00 = td/3.0 + td*(td-1.0)/2.0 + (td-1.0)*td*(2.0*td-1.0)/6.0;
            double sum01 = td/2.0 + td*(td-1.0)/2.0;
            pu00 = 1.0 + td*td + qd*sum00;
            pu01 = td + qd*sum01;
            pu11 = 1.0 + qd*td;
        }

        // ---- final structured inverse of the 132x132 filtered covariance ----
        float La[4] = {__fdividef(1.0f,a[0]), __fdividef(1.0f,a[1]),
                       __fdividef(1.0f,a[2]), __fdividef(1.0f,a[3])};
        float Xb[4][4];
#pragma unroll
        for (int g=0; g<4; ++g)
#pragma unroll
            for (int h=0; h<4; ++h)
                Xb[g][h] = ((g==h)?1.0f:0.0f) + 32.0f*La[g]*B[g][h];
        // general 4x4 inverse of Xb (not symmetric)
        float Yb[4][4];
        {
            float a00=Xb[0][0], a01=Xb[0][1], a02=Xb[0][2], a03=Xb[0][3];
            float a10=Xb[1][0], a11=Xb[1][1], a12=Xb[1][2], a13=Xb[1][3];
            float a20=Xb[2][0], a21=Xb[2][1], a22=Xb[2][2], a23=Xb[2][3];
            float a30=Xb[3][0], a31=Xb[3][1], a32=Xb[3][2], a33=Xb[3][3];
            float s0=a00*a11-a10*a01, s1=a00*a12-a10*a02, s2=a00*a13-a10*a03;
            float s3=a01*a12-a11*a02, s4=a01*a13-a11*a03, s5=a02*a13-a12*a03;
            float c5=a22*a33-a32*a23, c4=a21*a33-a31*a23, c3=a21*a32-a31*a22;
            float c2=a20*a33-a30*a23, c1=a20*a32-a30*a22, c0=a20*a31-a30*a21;
            float det = s0*c5 - s1*c4 + s2*c3 + s3*c2 - s4*c1 + s5*c0;
            float id = __fdividef(1.0f, det);
            Yb[0][0]=( a11*c5 - a12*c4 + a13*c3)*id;
            Yb[0][1]=(-a01*c5 + a02*c4 - a03*c3)*id;
            Yb[0][2]=( a31*s5 - a32*s4 + a33*s3)*id;
            Yb[0][3]=(-a21*s5 + a22*s4 - a23*s3)*id;
            Yb[1][0]=(-a10*c5 + a12*c2 - a13*c1)*id;
            Yb[1][1]=( a00*c5 - a02*c2 + a03*c1)*id;
            Yb[1][2]=(-a30*s5 + a32*s2 - a33*s1)*id;
            Yb[1][3]=( a20*s5 - a22*s2 + a23*s1)*id;
            Yb[2][0]=( a10*c4 - a11*c2 + a13*c0)*id;
            Yb[2][1]=(-a00*c4 + a01*c2 - a03*c0)*id;
            Yb[2][2]=( a30*s4 - a31*s2 + a33*s0)*id;
            Yb[2][3]=(-a20*s4 + a21*s2 - a23*s0)*id;
            Yb[3][0]=(-a10*c3 + a11*c1 - a12*c0)*id;
            Yb[3][1]=( a00*c3 - a01*c1 + a02*c0)*id;
            Yb[3][2]=(-a30*s3 + a31*s1 - a32*s0)*id;
            Yb[3][3]=( a20*s3 - a21*s1 + a22*s0)*id;
        }
        float G[4][4];
#pragma unroll
        for (int g=0; g<4; ++g)
#pragma unroll
            for (int h=0; h<4; ++h) {
                float s=0.0f;
#pragma unroll
                for (int k=0; k<4; ++k) s += B[g][k]*Yb[k][h];
                G[g][h] = La[g]*s*La[h];
            }
        float M4[4][4];
#pragma unroll
        for (int g=0; g<4; ++g)
#pragma unroll
            for (int h=0; h<4; ++h)
                M4[g][h] = ((g==h)?La[g]:0.0f) - 32.0f*G[g][h];
        float MC[4][2];
#pragma unroll
        for (int g=0; g<4; ++g) {
            float t0=0.0f, t1=0.0f;
#pragma unroll
            for (int k=0; k<4; ++k) { t0 += M4[g][k]*C[k][0]; t1 += M4[g][k]*C[k][1]; }
            MC[g][0]=t0; MC[g][1]=t1;
        }
        float ss00=p00, ss01=p02, ss11=p22;
#pragma unroll
        for (int g=0; g<4; ++g) {
            ss00 -= 32.0f*C[g][0]*MC[g][0];
            ss01 -= 32.0f*C[g][0]*MC[g][1];
            ss11 -= 32.0f*C[g][1]*MC[g][1];
        }
        {
            float det = ss00*ss11 - ss01*ss01;
            float id = __fdividef(1.0f, det);
            sSsInv[0][0] =  ss11*id;
            sSsInv[0][1] = -ss01*id;
            sSsInv[1][0] = -ss01*id;
            sSsInv[1][1] =  ss00*id;
        }
#pragma unroll
        for (int g=0; g<4; ++g) {
            float e0 = -(MC[g][0]*sSsInv[0][0] + MC[g][1]*sSsInv[1][0]);
            float e1 = -(MC[g][0]*sSsInv[0][1] + MC[g][1]*sSsInv[1][1]);
            sE[g][0]=e0; sE[g][1]=e1;
        }
#pragma unroll
        for (int g=0; g<4; ++g)
#pragma unroll
            for (int h=0; h<4; ++h)
                sPhi[g][h] = -G[g][h] - (sE[g][0]*MC[h][0] + sE[g][1]*MC[h][1]);
#pragma unroll
        for (int g=0; g<4; ++g) sLam4[g] = La[g];
        {
            double det = pu00*pu11 - pu01*pu01;
            double idd = 1.0/det;
            sPu[0] = (float)( pu11*idd);
            sPu[1] = (float)(-pu01*idd);
            sPu[2] = (float)( pu00*idd);
        }
        sll = ll;
    }

    __syncthreads();

    // ---- expand to the 132x132 precision matrix (+ ll at out[0]) ----
    const int off = (out_size >= 17425) ? 1 : 0;
    if (threadIdx.x == 0 && off) out[0] = (float)sll;

    for (int e = threadIdx.x; e < 17424; e += blockDim.x) {
        int r = e / 132, c = e % 132;
        float val = 0.0f;
        if (r < 128 && c < 128) {
            int g = (r & 1) + ((r >= 64) ? 2 : 0);
            int h = (c & 1) + ((c >= 64) ? 2 : 0);
            val = sPhi[g][h];
            if (r == c) val += sLam4[g];
        } else if (r < 128) {
            int g = (r & 1) + ((r >= 64) ? 2 : 0);
            int j = c - 128;
            if (j == 0) val = sE[g][0];
            else if (j == 2) val = sE[g][1];
        } else if (c < 128) {
            int h = (c & 1) + ((c >= 64) ? 2 : 0);
            int i = r - 128;
            if (i == 0) val = sE[h][0];
            else if (i == 2) val = sE[h][1];
        } else {
            int i = r - 128, j = c - 128;
            if ((i == 0 || i == 2) && (j == 0 || j == 2))
                val = sSsInv[i >> 1][j >> 1];
            else if (i == 1 && j == 1) val = sPu[0];
            else if ((i == 1 && j == 3) || (i == 3 && j == 1)) val = sPu[1];
            else if (i == 3 && j == 3) val = sPu[2];
        }
        out[off + e] = (float)val;
    }
}

extern "C" void kernel_launch(void* const* d_in, const int* in_sizes, int n_in,
                              void* d_out, int out_size) {
    const float* track       = (const float*)d_in[0];
    const float* bias_scales = (const float*)d_in[1];
    const float* obs_noise   = (const float*)d_in[2];
    const float* trans_noise = (const float*)d_in[3];
    float* out = (float*)d_out;
    hmm_kernel<<<1, 256>>>(track, bias_scales, obs_noise, trans_noise, out, out_size);
}